// round 5
// baseline (speedup 1.0000x reference)
#include <cuda_runtime.h>
#include <cuda_bf16.h>

#define N_CTRL 64
#define N_EVAL 2001
#define NPTS   (N_EVAL * N_EVAL)
#define DEG 3
#define INV_INTERNAL (1.0f / 61.0f)   // 60 internal knots at k/61, k=1..60

// ---------------- device scratch (no allocations allowed) ----------------
__device__ float4 g_Bu[N_EVAL];
__device__ float4 g_Bv[N_EVAL];
__device__ int    g_su[N_EVAL];
__device__ int    g_sv[N_EVAL];

__device__ __forceinline__ float knotf(int j) {
    if (j <= DEG) return 0.0f;
    if (j >= N_CTRL) return 1.0f;
    return (float)(j - DEG) * INV_INTERNAL;
}

// span = clip(searchsorted(knots, t, 'right') - 1, p, n_ctrl-1), analytic
__device__ __forceinline__ int find_span(float t) {
    int k = (int)floorf(t * 61.0f);
    if (k < 0) k = 0;
    if (k > 60) k = 60;
    if (k < 60 && (float)(k + 1) * INV_INTERNAL <= t) ++k;
    if (k > 0  && (float)k * INV_INTERNAL > t)        --k;
    return DEG + k;
}

// Cox-de-Boor (NURBS book A2.2), p=3
__device__ __forceinline__ void basis_funcs(float u, int span, float N[4]) {
    float left[4], right[4];
    N[0] = 1.0f;
    #pragma unroll
    for (int j = 1; j <= DEG; ++j) {
        left[j]  = u - knotf(span + 1 - j);
        right[j] = knotf(span + j) - u;
        float saved = 0.0f;
        #pragma unroll
        for (int r = 0; r < j; ++r) {
            float temp = N[r] / (right[r + 1] + left[j - r]);
            N[r] = saved + right[r + 1] * temp;
            saved = left[j - r] * temp;
        }
        N[j] = saved;
    }
}

// ---------------- kernel 1: spans + basis (tiny) ----------------
__global__ void nurbs_prep_kernel(const float* __restrict__ pu,
                                  const float* __restrict__ pv) {
    int i = blockIdx.x * blockDim.x + threadIdx.x;
    if (i >= N_EVAL) return;
    {
        float u = pu[i];
        int s = find_span(u);
        float B[4];
        basis_funcs(u, s, B);
        g_Bu[i] = make_float4(B[0], B[1], B[2], B[3]);
        g_su[i] = s;
    }
    {
        float v = pv[i];
        int s = find_span(v);
        float B[4];
        basis_funcs(v, s, B);
        g_Bv[i] = make_float4(B[0], B[1], B[2], B[3]);
        g_sv[i] = s;
    }
}

// ---------------- kernel 2: flat-index eval ----------------
// Block owns 1024 consecutive flat points g = u*2001 + v (touches <= 2 u-rows).
// Warp owns 128 consecutive points; lane handles points gw0 + k*32 + lane so
// every load is coalesced; results staged in smem so global stores are
// contiguous 16B-aligned STG.128 (minimum wavefronts).
#define TPB 256
#define VPT 4
#define PTS_BLK (TPB * VPT)   // 1024

__global__ __launch_bounds__(TPB) void nurbs_eval_kernel(const float* __restrict__ cp,
                                                         float* __restrict__ out) {
    __shared__ float4 s_curve[2][N_CTRL];       // 2 KB: collapsed curves, rows u0,u0+1
    __shared__ float4 s_stage4[TPB * 3];        // 12 KB: per-warp store staging

    const int tid    = threadIdx.x;
    const int g0_blk = blockIdx.x * PTS_BLK;
    const int u0     = g0_blk / N_EVAL;
    const int row_base = u0 * N_EVAL;

    // prologue: u-collapse for the (at most) 2 rows this block touches
    if (tid < 128) {
        const int r = tid >> 6;
        const int j = tid & 63;
        int u = u0 + r;
        if (u > N_EVAL - 1) u = N_EVAL - 1;
        const float4 bu = g_Bu[u];
        const int    su = g_su[u];
        const float* base = cp + ((su - DEG) * N_CTRL + j) * 3;
        float w[4] = {bu.x, bu.y, bu.z, bu.w};
        float cx = 0.f, cy = 0.f, cz = 0.f;
        #pragma unroll
        for (int a = 0; a < 4; ++a) {
            const float* q = base + a * (N_CTRL * 3);
            cx += w[a] * q[0];
            cy += w[a] * q[1];
            cz += w[a] * q[2];
        }
        s_curve[r][j] = make_float4(cx, cy, cz, 0.f);
    }
    __syncthreads();

    const int lane = tid & 31;
    const int warp = tid >> 5;
    const int gw0  = g0_blk + warp * 128;
    const bool full = (g0_blk + PTS_BLK) <= NPTS;

    float res[VPT * 3];
    #pragma unroll
    for (int k = 0; k < VPT; ++k) {
        int g = gw0 + k * 32 + lane;            // coalesced across lanes
        int gg = g < NPTS ? g : NPTS - 1;
        int v = gg - row_base;
        int r = 0;
        if (v >= N_EVAL) { v -= N_EVAL; r = 1; }
        const float4 bv = g_Bv[v];
        const int    o  = g_sv[v] - DEG;
        const float4 c0 = s_curve[r][o + 0];
        const float4 c1 = s_curve[r][o + 1];
        const float4 c2 = s_curve[r][o + 2];
        const float4 c3 = s_curve[r][o + 3];
        res[k * 3 + 0] = bv.x * c0.x + bv.y * c1.x + bv.z * c2.x + bv.w * c3.x;
        res[k * 3 + 1] = bv.x * c0.y + bv.y * c1.y + bv.z * c2.y + bv.w * c3.y;
        res[k * 3 + 2] = bv.x * c0.z + bv.y * c1.z + bv.z * c2.z + bv.w * c3.z;
    }

    if (full) {
        // stage: float index (point-in-warp)*3 + c ; stride-3 words => conflict-free
        float* st = (float*)(s_stage4 + warp * 96);
        #pragma unroll
        for (int k = 0; k < VPT; ++k) {
            int pi = k * 32 + lane;
            st[pi * 3 + 0] = res[k * 3 + 0];
            st[pi * 3 + 1] = res[k * 3 + 1];
            st[pi * 3 + 2] = res[k * 3 + 2];
        }
        __syncwarp();
        // drain: 96 float4 per warp, contiguous + 16B-aligned in gmem
        const float4* src = s_stage4 + warp * 96;
        float4* dst = (float4*)(out + (size_t)gw0 * 3);
        #pragma unroll
        for (int i = 0; i < 3; ++i) {
            dst[i * 32 + lane] = src[i * 32 + lane];
        }
    } else {
        // tail block: guarded scalar stores
        #pragma unroll
        for (int k = 0; k < VPT; ++k) {
            int g = gw0 + k * 32 + lane;
            if (g < NPTS) {
                out[(size_t)g * 3 + 0] = res[k * 3 + 0];
                out[(size_t)g * 3 + 1] = res[k * 3 + 1];
                out[(size_t)g * 3 + 2] = res[k * 3 + 2];
            }
        }
    }
}

extern "C" void kernel_launch(void* const* d_in, const int* in_sizes, int n_in,
                              void* d_out, int out_size) {
    const float* cp = (const float*)d_in[0];   // [64,64,3]
    const float* pu = (const float*)d_in[1];   // [2001]
    const float* pv = (const float*)d_in[2];   // [2001]
    float* out = (float*)d_out;

    nurbs_prep_kernel<<<(N_EVAL + 255) / 256, 256>>>(pu, pv);
    nurbs_eval_kernel<<<(NPTS + PTS_BLK - 1) / PTS_BLK, TPB>>>(cp, out);
}

// round 6
// speedup vs baseline: 1.1767x; 1.1767x over previous
#include <cuda_runtime.h>
#include <cuda_bf16.h>

#define N_CTRL 64
#define N_EVAL 2001
#define DEG 3
#define INV_INTERNAL (1.0f / 61.0f)   // 60 internal knots at k/61, k=1..60

// ---------------- device scratch (no allocations allowed) ----------------
__device__ float4 g_Bu[N_EVAL];
__device__ float4 g_Bv[N_EVAL];
__device__ int    g_su[N_EVAL];
__device__ int    g_sv[N_EVAL];

__device__ __forceinline__ float knotf(int j) {
    if (j <= DEG) return 0.0f;
    if (j >= N_CTRL) return 1.0f;
    return (float)(j - DEG) * INV_INTERNAL;
}

// span = clip(searchsorted(knots, t, 'right') - 1, p, n_ctrl-1), analytic
__device__ __forceinline__ int find_span(float t) {
    int k = (int)floorf(t * 61.0f);
    if (k < 0) k = 0;
    if (k > 60) k = 60;
    if (k < 60 && (float)(k + 1) * INV_INTERNAL <= t) ++k;
    if (k > 0  && (float)k * INV_INTERNAL > t)        --k;
    return DEG + k;
}

// Cox-de-Boor (NURBS book A2.2), p=3
__device__ __forceinline__ void basis_funcs(float u, int span, float N[4]) {
    float left[4], right[4];
    N[0] = 1.0f;
    #pragma unroll
    for (int j = 1; j <= DEG; ++j) {
        left[j]  = u - knotf(span + 1 - j);
        right[j] = knotf(span + j) - u;
        float saved = 0.0f;
        #pragma unroll
        for (int r = 0; r < j; ++r) {
            float temp = N[r] / (right[r + 1] + left[j - r]);
            N[r] = saved + right[r + 1] * temp;
            saved = left[j - r] * temp;
        }
        N[j] = saved;
    }
}

// ---------------- kernel 1: spans + basis for both axes (tiny) ----------------
__global__ void nurbs_prep_kernel(const float* __restrict__ pu,
                                  const float* __restrict__ pv) {
    int i = blockIdx.x * blockDim.x + threadIdx.x;
    if (i >= N_EVAL) return;
    {
        float u = pu[i];
        int s = find_span(u);
        float B[4];
        basis_funcs(u, s, B);
        g_Bu[i] = make_float4(B[0], B[1], B[2], B[3]);
        g_su[i] = s;
    }
    {
        float v = pv[i];
        int s = find_span(v);
        float B[4];
        basis_funcs(v, s, B);
        g_Bv[i] = make_float4(B[0], B[1], B[2], B[3]);
        g_sv[i] = s;
    }
}

// ---------------- kernel 2: fused collapse + v-eval ----------------
// 4 u-rows per block, v-range split across VSPLIT blocks for occupancy.
#define TPB 256
#define U_TILE 4
#define VSPLIT 2
#define VCHUNK ((N_EVAL + VSPLIT - 1) / VSPLIT)   // 1001

__global__ __launch_bounds__(TPB) void nurbs_eval_kernel(const float* __restrict__ cp,
                                                         float* __restrict__ out) {
    __shared__ float4 s_curve[U_TILE][N_CTRL];   // 4 KB

    const int u0  = blockIdx.y * U_TILE;
    const int tid = threadIdx.x;
    const int nrows  = (N_EVAL - u0) < U_TILE ? (N_EVAL - u0) : U_TILE;
    const int vstart = blockIdx.x * VCHUNK;
    const int vend   = (vstart + VCHUNK) < N_EVAL ? (vstart + VCHUNK) : N_EVAL;

    // cooperative u-collapse: tid -> (row r, ctrl col j); 256 = 4*64 exact
    {
        const int r = tid >> 6;        // 0..3
        const int j = tid & 63;        // 0..63
        if (r < nrows) {
            const float4 bu = g_Bu[u0 + r];
            const int    su = g_su[u0 + r];
            const float* base = cp + ((su - DEG) * N_CTRL + j) * 3;
            float w[4] = {bu.x, bu.y, bu.z, bu.w};
            float cx = 0.f, cy = 0.f, cz = 0.f;
            #pragma unroll
            for (int a = 0; a < 4; ++a) {
                const float* q = base + a * (N_CTRL * 3);
                cx += w[a] * q[0];
                cy += w[a] * q[1];
                cz += w[a] * q[2];
            }
            s_curve[r][j] = make_float4(cx, cy, cz, 0.f);
        }
    }
    __syncthreads();

    // v eval: adjacent lanes -> adjacent v (coalesced Bv/sv); direct stores.
    // unroll 2 => 8 independent FMA chains in flight per thread.
    #pragma unroll 2
    for (int p = vstart + tid; p < vend; p += TPB) {
        const float4 bv = g_Bv[p];
        const int    o  = g_sv[p] - DEG;
        #pragma unroll
        for (int r = 0; r < U_TILE; ++r) {
            if (r < nrows) {
                const float4 c0 = s_curve[r][o + 0];
                const float4 c1 = s_curve[r][o + 1];
                const float4 c2 = s_curve[r][o + 2];
                const float4 c3 = s_curve[r][o + 3];
                float x = bv.x * c0.x + bv.y * c1.x + bv.z * c2.x + bv.w * c3.x;
                float y = bv.x * c0.y + bv.y * c1.y + bv.z * c2.y + bv.w * c3.y;
                float z = bv.x * c0.z + bv.y * c1.z + bv.z * c2.z + bv.w * c3.z;
                float* dst = out + ((size_t)(u0 + r) * N_EVAL + p) * 3;
                dst[0] = x;
                dst[1] = y;
                dst[2] = z;
            }
        }
    }
}

extern "C" void kernel_launch(void* const* d_in, const int* in_sizes, int n_in,
                              void* d_out, int out_size) {
    const float* cp = (const float*)d_in[0];   // [64,64,3]
    const float* pu = (const float*)d_in[1];   // [2001]
    const float* pv = (const float*)d_in[2];   // [2001]
    float* out = (float*)d_out;

    nurbs_prep_kernel<<<(N_EVAL + 255) / 256, 256>>>(pu, pv);
    dim3 grid(VSPLIT, (N_EVAL + U_TILE - 1) / U_TILE);
    nurbs_eval_kernel<<<grid, TPB>>>(cp, out);
}